// round 7
// baseline (speedup 1.0000x reference)
#include <cuda_runtime.h>
#include <cuda_bf16.h>
#include <cstdint>

// Problem shape
#define NB   256
#define NH   512
#define NW   512
#define HW   (NH * NW)          // 262144 = 1<<18
#define NTOT ((size_t)NB * HW)  // 67108864
#define BPB  8                  // blocks per batch -> 2 waves at occ 8/SM
#define NBLK (NB * BPB)         // 2048
#define CHUNK (HW / BPB)        // 32768 elems per block
#define FWHM 0.5f
#define DHW  32                 // h/H_SCALE = w/W_SCALE = 512/16

// Scratch (no allocations allowed — __device__ globals, zeroed at load)
__device__ unsigned long long g_keyblk[NBLK];  // per-block argmax key
__device__ double   g_part1[NBLK];             // per-block unweighted sqdiff sum
__device__ double   g_part2[NB];               // per-batch window correction
__device__ unsigned g_bdone[NB];               // per-batch ticket (self-resetting)
__device__ unsigned g_done;                    // global ticket  (self-resetting)

// ---------------------------------------------------------------------------
// ONE fused kernel, TWO waves:
//  phase A (2048 blocks): stream 32K elems/block of both arrays once;
//     accumulate unweighted sum((o-t)^2) and per-block first-argmax of target.
//     key = (float_bits << 32) | (0xFFFFFFFF - idx): target in [0,1) so uint
//     order == float order; larger ~idx under max => first-max tie-break.
//  phase B (last block of each batch): batches of wave 1 finish at ~T/2, so
//     their <=64x64 window fix-ups run UNDER wave 2's streaming. Only the
//     final wave's fix-ups (~108, one per SM) land in the tail.
//  phase C (globally last block): deterministic sum of all partials -> mean.
// ---------------------------------------------------------------------------
__global__ __launch_bounds__(256, 8)
void fused_kernel(const float* __restrict__ outp, const float* __restrict__ tgtp,
                  float* __restrict__ res) {
    const int batch = blockIdx.x >> 3;        // / BPB
    const int chunk = blockIdx.x & (BPB - 1);
    const size_t base = (size_t)batch * HW + (size_t)chunk * CHUNK;
    const float4* __restrict__ o4 = (const float4*)(outp + base);
    const float4* __restrict__ t4 = (const float4*)(tgtp + base);
    const unsigned idx0 = (unsigned)(chunk * CHUNK);
    const int tid = threadIdx.x;

    // ---------------- phase A: streaming ----------------
    float s = 0.0f;
    float mval = -1.0f;
    unsigned midx = 0u;

    #pragma unroll 4
    for (int i = tid; i < CHUNK / 4; i += 256) {
        float4 t = t4[i];
        float4 o = o4[i];
        float d0 = o.x - t.x, d1 = o.y - t.y, d2 = o.z - t.z, d3 = o.w - t.w;
        s += d0 * d0 + d1 * d1 + d2 * d2 + d3 * d3;

        float m4 = fmaxf(fmaxf(t.x, t.y), fmaxf(t.z, t.w));
        if (m4 > mval) {                       // rare after warmup
            mval = m4;
            unsigned eb = idx0 + 4u * (unsigned)i;
            midx = (t.x == m4) ? eb
                 : (t.y == m4) ? eb + 1u
                 : (t.z == m4) ? eb + 2u
                 :               eb + 3u;      // in-quad first-match
        }
    }

    unsigned long long bk =
        ((unsigned long long)__float_as_uint(mval) << 32) | (0xFFFFFFFFu - midx);

    #pragma unroll
    for (int off = 16; off > 0; off >>= 1) {
        s += __shfl_down_sync(0xFFFFFFFFu, s, off);
        unsigned long long ok = __shfl_down_sync(0xFFFFFFFFu, bk, off);
        if (ok > bk) bk = ok;
    }

    __shared__ float ssum[8];
    __shared__ unsigned long long skey[8];
    __shared__ int s_fix, s_last;
    const int w = tid >> 5, l = tid & 31;
    if (l == 0) { ssum[w] = s; skey[w] = bk; }
    __syncthreads();

    if (tid == 0) {
        float ts = 0.0f;
        unsigned long long tk = skey[0];
        #pragma unroll
        for (int i = 0; i < 8; i++) {
            ts += ssum[i];
            if (skey[i] > tk) tk = skey[i];
        }
        g_part1[blockIdx.x]  = (double)ts;
        g_keyblk[blockIdx.x] = tk;
        __threadfence();
        unsigned t = atomicAdd(&g_bdone[batch], 1u);
        s_fix = (t == BPB - 1) ? 1 : 0;
        if (s_fix) g_bdone[batch] = 0;         // reset for next graph replay
    }
    __syncthreads();

    // -------- phase B: per-batch window fix-up (overlaps wave-2 streaming) --------
    if (s_fix) {
        __threadfence();  // acquire: other chunks' g_keyblk stores visible
        unsigned long long key = g_keyblk[BPB * batch];
        #pragma unroll
        for (int j = 1; j < BPB; j++) {
            unsigned long long k = g_keyblk[BPB * batch + j];
            if (k > key) key = k;
        }
        const float mv = __uint_as_float((unsigned)(key >> 32));

        float fs = 0.0f;
        if (mv >= FWHM) {
            const unsigned pos = 0xFFFFFFFFu - (unsigned)(key & 0xFFFFFFFFu);
            const int ph = (int)(pos >> 9);
            const int pw = (int)(pos & 511u);
            const int top   = max(ph - DHW, 0);
            const int bot   = min(ph + DHW, NH);
            const int left  = max(pw - DHW, 0);
            const int right = min(pw + DHW, NW);
            const int Lh = bot - top, Lw = right - left;
            const float dh = (float)max((Lh + 1) / 2 - 1, 1);
            const float dw = (float)max((Lw + 1) / 2 - 1, 1);
            const size_t bbase = (size_t)batch << 18;

            const int c  = tid & 63;            // column within window
            const int r0 = tid >> 6;            // 4 row-lanes, stride 4
            if (c < Lw) {
                const float vw = 1.0f + 9.0f * (float)min(c, Lw - 1 - c) / dw;
                #pragma unroll
                for (int j = 0; j < 16; j++) {
                    const int r = r0 + 4 * j;
                    if (r < Lh) {
                        const float vh = 1.0f + 9.0f * (float)min(r, Lh - 1 - r) / dh;
                        const size_t idx = bbase + ((size_t)(top + r) << 9)
                                                 + (size_t)(left + c);
                        const float d = outp[idx] - tgtp[idx];
                        fs += d * d * (vh * vw - 1.0f);
                    }
                }
            }
        }

        #pragma unroll
        for (int off = 16; off > 0; off >>= 1)
            fs += __shfl_down_sync(0xFFFFFFFFu, fs, off);
        if (l == 0) ssum[w] = fs;
        __syncthreads();
        if (tid == 0) {
            float t2 = 0.0f;
            #pragma unroll
            for (int i = 0; i < 8; i++) t2 += ssum[i];
            g_part2[batch] = (double)t2;
        }
    }

    // ---------------- phase C: global last block finalizes ----------------
    if (tid == 0) {
        __threadfence();
        unsigned ticket = atomicAdd(&g_done, 1u);
        s_last = (ticket == NBLK - 1) ? 1 : 0;
        if (s_last) g_done = 0;                // reset for next graph replay
    }
    __syncthreads();

    if (s_last) {
        __threadfence();                        // all partials visible
        __shared__ double sh[256];
        double acc = g_part2[tid];
        #pragma unroll
        for (int j = 0; j < 8; j++)
            acc += g_part1[tid + 256 * j];
        sh[tid] = acc;
        __syncthreads();
        #pragma unroll
        for (int st = 128; st > 0; st >>= 1) {
            if (tid < st) sh[tid] += sh[tid + st];
            __syncthreads();
        }
        if (tid == 0)
            res[0] = (float)(sh[0] * (1.0 / (double)NTOT));
    }
}

extern "C" void kernel_launch(void* const* d_in, const int* in_sizes, int n_in,
                              void* d_out, int out_size) {
    const float* outp = (const float*)d_in[0];   // "output" (normal)
    const float* tgtp = (const float*)d_in[1];   // "target" (uniform)
    float* res = (float*)d_out;

    fused_kernel<<<NBLK, 256>>>(outp, tgtp, res);
}